// round 2
// baseline (speedup 1.0000x reference)
#include <cuda_runtime.h>
#include <cstdint>

// Problem constants (fixed by the dataset)
#define NN   2048   // nodes
#define DD   16     // input dim
#define HH   64     // hidden
#define G4   256    // 4*H
#define NCTA 128    // CTAs (1 per SM, all co-resident: 128 <= 148 SMs)
#define ROWS 16     // rows (nodes) per CTA  -> NCTA*ROWS == NN
#define NTH  512    // threads per CTA (16 warps, warp w owns row n0+w)
#define KT   128    // k-tile for A@q

typedef unsigned long long u64;

// Global scratch (static __device__ arrays are allowed; no cudaMalloc)
__device__ float g_q[2][NN][HH];   // double-buffered q = tanh(h @ W_q + b_q)
__device__ int   g_bar = 0;        // grid barrier counter (self-resetting)

struct Smem {
  float W_ih[DD][G4];       // 16 KB
  float W_hh[HH][G4];       // 64 KB
  float W_q [HH][HH];       // 16 KB
  float bias[G4];           // 1 KB
  float b_q [HH];
  float W_d [HH];
  float h_loc[ROWS][HH];    // 4 KB  (CTA-private hidden state)
  float c_loc[ROWS][HH];    // 4 KB  (CTA-private cell state)
  float q_tile[KT][HH];     // 32 KB (staged q k-tile)
  float A_dup[ROWS][KT][2]; // 16 KB (A values duplicated as {a,a} pairs for FFMA2)
};

__device__ __forceinline__ void fma2(u64& d, u64 a, u64 b) {
  asm("fma.rn.f32x2 %0, %1, %2, %0;" : "+l"(d) : "l"(a), "l"(b));
}
__device__ __forceinline__ u64 pack2(float v) {
  u64 r; asm("mov.b64 %0, {%1, %1};" : "=l"(r) : "f"(v)); return r;
}
__device__ __forceinline__ float2 unpack2(u64 v) {
  float2 r; asm("mov.b64 {%0, %1}, %2;" : "=f"(r.x), "=f"(r.y) : "l"(v)); return r;
}
__device__ __forceinline__ float sigm_f(float x)  { return 1.0f / (1.0f + __expf(-x)); }
__device__ __forceinline__ float tanh_f(float x)  { return 1.0f - 2.0f / (__expf(2.0f * x) + 1.0f); }

__global__ void __launch_bounds__(NTH, 1)
rgcn_kernel(const float* __restrict__ x,    const float* __restrict__ A,
            const float* __restrict__ W_ih, const float* __restrict__ W_hh,
            const float* __restrict__ bias, const float* __restrict__ W_q,
            const float* __restrict__ b_q,  const float* __restrict__ W_d,
            const float* __restrict__ b_d,  float* __restrict__ out, int T)
{
  extern __shared__ unsigned char smem_raw[];
  Smem& s = *reinterpret_cast<Smem*>(smem_raw);

  const int tid  = threadIdx.x;
  const int wid  = tid >> 5;
  const int lane = tid & 31;
  const int n    = blockIdx.x * ROWS + wid;   // this warp's node row
  const int j0   = 2 * lane;                  // this lane's column pair

  // ---- load constant weights into shared (persist for whole kernel) ----
  for (int i = tid; i < DD * G4; i += NTH) (&s.W_ih[0][0])[i] = W_ih[i];
  for (int i = tid; i < HH * G4; i += NTH) (&s.W_hh[0][0])[i] = W_hh[i];
  for (int i = tid; i < HH * HH; i += NTH) (&s.W_q[0][0])[i]  = W_q[i];
  for (int i = tid; i < G4;      i += NTH) s.bias[i] = bias[i];
  for (int i = tid; i < HH;      i += NTH) { s.b_q[i] = b_q[i]; s.W_d[i] = W_d[i]; }
  for (int i = tid; i < ROWS * HH; i += NTH) {
    (&s.h_loc[0][0])[i] = 0.0f;
    (&s.c_loc[0][0])[i] = 0.0f;
  }
  __syncthreads();
  const float bd = __ldg(b_d);

  const float* Arow = A + (size_t)n * NN;

  for (int t = 0; t < T; ++t) {
    const int p = t & 1;

    // ===== phase 1: q = tanh(h_{t-1} @ W_q + b_q) for own rows, write global =====
    {
      float2 acc = make_float2(s.b_q[j0], s.b_q[j0 + 1]);
      #pragma unroll 8
      for (int k = 0; k < HH; ++k) {
        const float hv = s.h_loc[wid][k];              // broadcast LDS
        const float2 wq = *reinterpret_cast<const float2*>(&s.W_q[k][j0]);
        acc.x = fmaf(hv, wq.x, acc.x);
        acc.y = fmaf(hv, wq.y, acc.y);
      }
      float2 qv = make_float2(tanh_f(acc.x), tanh_f(acc.y));
      *reinterpret_cast<float2*>(&g_q[p][n][j0]) = qv;
    }

    // ===== grid barrier (release q writes, acquire others' q) =====
    __threadfence();           // make this thread's q stores visible GPU-wide
    __syncthreads();
    if (tid == 0) {
      atomicAdd(&g_bar, 1);
      const int target = NCTA * (t + 1);
      while (*((volatile int*)&g_bar) < target) { }
      __threadfence();         // acquire; scope>=cluster => CCTL.IVALL (L1 invalidate)
    }
    __syncthreads();

    // ===== phase 2: Aq = A @ q (k-tiled), gates, state update, output =====
    u64 aq = 0ull;   // packed {Aq[n][j0], Aq[n][j0+1]}
    #pragma unroll 1
    for (int kt = 0; kt < NN / KT; ++kt) {
      // stage q tile (L2-only loads: q was written by other SMs)
      {
        const float4* src = reinterpret_cast<const float4*>(&g_q[p][kt * KT][0]);
        float4* dst = reinterpret_cast<float4*>(&s.q_tile[0][0]);
        #pragma unroll
        for (int i = 0; i < (KT * HH / 4) / NTH; ++i)
          dst[tid + i * NTH] = __ldcg(src + tid + i * NTH);
      }
      // stage this warp's A row chunk, duplicated as {a,a} pairs for FFMA2 broadcast
      {
        const float4 av = __ldg(reinterpret_cast<const float4*>(Arow + kt * KT + lane * 4));
        u64* d = reinterpret_cast<u64*>(&s.A_dup[wid][lane * 4][0]);
        d[0] = pack2(av.x); d[1] = pack2(av.y); d[2] = pack2(av.z); d[3] = pack2(av.w);
      }
      __syncthreads();
      // 1 FFMA2 + 2 LDS.64 per k per warp
      #pragma unroll 8
      for (int k = 0; k < KT; ++k) {
        const u64 a2 = *reinterpret_cast<const u64*>(&s.A_dup[wid][k][0]); // broadcast
        const u64 q2 = *reinterpret_cast<const u64*>(&s.q_tile[k][j0]);
        fma2(aq, a2, q2);
      }
      __syncthreads();
    }

    // gates = x_t @ W_ih + h @ W_hh + bias  (lane handles col pairs in i,f,g,o blocks)
    u64 accg[4];
    #pragma unroll
    for (int m = 0; m < 4; ++m)
      accg[m] = *reinterpret_cast<const u64*>(&s.bias[m * HH + j0]);

    {
      float xreg = (lane < DD) ? __ldg(&x[((size_t)n * T + t) * DD + lane]) : 0.0f;
      #pragma unroll
      for (int d = 0; d < DD; ++d) {
        const u64 xd2 = pack2(__shfl_sync(0xffffffffu, xreg, d));
        #pragma unroll
        for (int m = 0; m < 4; ++m)
          fma2(accg[m], xd2, *reinterpret_cast<const u64*>(&s.W_ih[d][m * HH + j0]));
      }
      #pragma unroll 4
      for (int k = 0; k < HH; ++k) {
        const u64 h2 = pack2(s.h_loc[wid][k]);      // broadcast LDS
        #pragma unroll
        for (int m = 0; m < 4; ++m)
          fma2(accg[m], h2, *reinterpret_cast<const u64*>(&s.W_hh[k][m * HH + j0]));
      }
    }

    // activations + state update
    {
      const float2 gi = unpack2(accg[0]);
      const float2 gf = unpack2(accg[1]);
      const float2 gg = unpack2(accg[2]);
      const float2 go = unpack2(accg[3]);
      const float2 aqv = unpack2(aq);
      const float2 cold = *reinterpret_cast<const float2*>(&s.c_loc[wid][j0]);

      const float i0 = sigm_f(gi.x), i1 = sigm_f(gi.y);
      const float f0 = sigm_f(gf.x), f1 = sigm_f(gf.y);
      const float gg0 = tanh_f(gg.x), gg1 = tanh_f(gg.y);
      const float o0 = sigm_f(go.x), o1 = sigm_f(go.y);

      const float c0 = f0 * (cold.x + aqv.x) + i0 * gg0;
      const float c1 = f1 * (cold.y + aqv.y) + i1 * gg1;
      const float h0 = o0 * tanh_f(c0);
      const float h1 = o1 * tanh_f(c1);

      *reinterpret_cast<float2*>(&s.c_loc[wid][j0]) = make_float2(c0, c1);
      *reinterpret_cast<float2*>(&s.h_loc[wid][j0]) = make_float2(h0, h1);

      // out[n, t] = h_t @ W_dense + b_dense   (warp reduction)
      float part = h0 * s.W_d[j0] + h1 * s.W_d[j0 + 1];
      #pragma unroll
      for (int off = 16; off > 0; off >>= 1)
        part += __shfl_down_sync(0xffffffffu, part, off);
      if (lane == 0) out[(size_t)n * T + t] = part + bd;
    }
    __syncwarp();   // h_loc/c_loc written by all lanes; phase 1 of t+1 reads all of them
  }

  // ===== self-resetting barrier counter: last CTA to finish zeroes it =====
  __syncthreads();
  if (tid == 0) {
    const int ticket = atomicAdd(&g_bar, 1);
    if (ticket == NCTA * (T + 1) - 1) {
      atomicExch(&g_bar, 0);     // persists to next launch / graph replay
    }
  }
}

extern "C" void kernel_launch(void* const* d_in, const int* in_sizes, int n_in,
                              void* d_out, int out_size) {
  const float* x    = (const float*)d_in[0];
  const float* A    = (const float*)d_in[1];
  const float* W_ih = (const float*)d_in[2];
  const float* W_hh = (const float*)d_in[3];
  const float* bias = (const float*)d_in[4];
  const float* W_q  = (const float*)d_in[5];
  const float* b_q  = (const float*)d_in[6];
  const float* W_d  = (const float*)d_in[7];
  const float* b_d  = (const float*)d_in[8];
  float* out = (float*)d_out;

  const int T = in_sizes[0] / (NN * DD);   // 365

  cudaFuncSetAttribute(rgcn_kernel,
                       cudaFuncAttributeMaxDynamicSharedMemorySize,
                       (int)sizeof(Smem));
  rgcn_kernel<<<NCTA, NTH, sizeof(Smem)>>>(x, A, W_ih, W_hh, bias,
                                           W_q, b_q, W_d, b_d, out, T);
}

// round 3
// speedup vs baseline: 1.7064x; 1.7064x over previous
#include <cuda_runtime.h>
#include <cstdint>

// Problem constants (fixed by the dataset)
#define NN   2048   // nodes
#define DD   16     // input dim
#define HH   64     // hidden
#define G4   256    // 4*H
#define NCTA 128    // CTAs (1 per SM, all co-resident: 128 <= 148 SMs)
#define ROWS 16     // rows (nodes) per CTA  -> NCTA*ROWS == NN
#define NTH  512    // threads per CTA (16 warps)
#define KT   128    // k-tile for A@q
#define NKT  (NN / KT)   // 16 tiles

typedef unsigned long long u64;

// Global scratch (static __device__ arrays are allowed; no cudaMalloc)
__device__ float g_q[2][NN][HH];           // double-buffered q = tanh(h @ W_q + b_q)
__device__ float g_Apack[(size_t)NN * NN * 2];  // A repacked: [blk][k][r-dup pairs], 32MB
__device__ int   g_bar = 0;                // grid barrier counter (self-resetting)

struct Smem {
  float W_ih[DD][G4];       // 16 KB
  float W_hh[HH][G4];       // 64 KB
  float W_q [HH][HH];       // 16 KB
  float bias[G4];           // 1 KB
  float b_q [HH];
  float W_d [HH];
  float h_loc[ROWS][HH];    // 4 KB  (CTA-private hidden state)
  float c_loc[ROWS][HH];    // 4 KB  (CTA-private cell state)
  float q_tile[KT][HH];     // 32 KB (staged q k-tile; reused as reduction buffer)
  float A_s[KT][2 * ROWS];  // 16 KB (A tile, rows duplicated as {a,a} pairs)
};

__device__ __forceinline__ void fma2(u64& d, u64 a, u64 b) {
  asm("fma.rn.f32x2 %0, %1, %2, %0;" : "+l"(d) : "l"(a), "l"(b));
}
__device__ __forceinline__ u64 pack2(float v) {
  u64 r; asm("mov.b64 %0, {%1, %1};" : "=l"(r) : "f"(v)); return r;
}
__device__ __forceinline__ float2 unpack2(u64 v) {
  float2 r; asm("mov.b64 {%0, %1}, %2;" : "=f"(r.x), "=f"(r.y) : "l"(v)); return r;
}
__device__ __forceinline__ float sigm_f(float x)  { return 1.0f / (1.0f + __expf(-x)); }
__device__ __forceinline__ float tanh_f(float x)  { return 1.0f - 2.0f / (__expf(2.0f * x) + 1.0f); }

__global__ void __launch_bounds__(NTH, 1)
rgcn_kernel(const float* __restrict__ x,    const float* __restrict__ A,
            const float* __restrict__ W_ih, const float* __restrict__ W_hh,
            const float* __restrict__ bias, const float* __restrict__ W_q,
            const float* __restrict__ b_q,  const float* __restrict__ W_d,
            const float* __restrict__ b_d,  float* __restrict__ out, int T)
{
  extern __shared__ unsigned char smem_raw[];
  Smem& s = *reinterpret_cast<Smem*>(smem_raw);

  const int tid  = threadIdx.x;
  const int wid  = tid >> 5;
  const int lane = tid & 31;
  const int n    = blockIdx.x * ROWS + wid;   // this warp's node row (q/gates/act phases)
  const int j0   = 2 * lane;                  // this lane's column pair
  const int rg   = wid & 1;                   // GEMM row group (rows rg*8 .. rg*8+7)
  const int ks   = wid >> 1;                  // GEMM k-slice within tile (16 k each)

  // ---- load constant weights into shared (persist for whole kernel) ----
  for (int i = tid; i < DD * G4; i += NTH) (&s.W_ih[0][0])[i] = W_ih[i];
  for (int i = tid; i < HH * G4; i += NTH) (&s.W_hh[0][0])[i] = W_hh[i];
  for (int i = tid; i < HH * HH; i += NTH) (&s.W_q[0][0])[i]  = W_q[i];
  for (int i = tid; i < G4;      i += NTH) s.bias[i] = bias[i];
  for (int i = tid; i < HH;      i += NTH) { s.b_q[i] = b_q[i]; s.W_d[i] = W_d[i]; }
  for (int i = tid; i < ROWS * HH; i += NTH) {
    (&s.h_loc[0][0])[i] = 0.0f;
    (&s.c_loc[0][0])[i] = 0.0f;
  }

  // ---- one-time repack of this CTA's A rows into {a,a} duplicated pairs ----
  // Layout: g_Apack[blk][k][2*r + {0,1}] = A[blk*16 + r][k]   (blk = blockIdx.x)
  {
    const float* arow = A + (size_t)n * NN;              // warp wid handles row wid
    float* dst = g_Apack + (size_t)blockIdx.x * NN * 2 * ROWS;
    #pragma unroll 1
    for (int c = 0; c < NN / 128; ++c) {                 // 16 chunks of 128 k per warp
      const int k0 = c * 128 + lane * 4;
      const float4 v = __ldg(reinterpret_cast<const float4*>(arow + k0));
      float2 d;
      d.x = v.x; d.y = v.x; *reinterpret_cast<float2*>(dst + (size_t)(k0 + 0) * (2 * ROWS) + 2 * wid) = d;
      d.x = v.y; d.y = v.y; *reinterpret_cast<float2*>(dst + (size_t)(k0 + 1) * (2 * ROWS) + 2 * wid) = d;
      d.x = v.z; d.y = v.z; *reinterpret_cast<float2*>(dst + (size_t)(k0 + 2) * (2 * ROWS) + 2 * wid) = d;
      d.x = v.w; d.y = v.w; *reinterpret_cast<float2*>(dst + (size_t)(k0 + 3) * (2 * ROWS) + 2 * wid) = d;
    }
  }
  __syncthreads();
  const float bd = __ldg(b_d);
  const float* apack_base = g_Apack + (size_t)blockIdx.x * NN * 2 * ROWS;

  for (int t = 0; t < T; ++t) {
    const int p = t & 1;

    // ===== phase 1: q = tanh(h_{t-1} @ W_q + b_q) for own row, write global =====
    {
      float2 acc = make_float2(s.b_q[j0], s.b_q[j0 + 1]);
      #pragma unroll 8
      for (int k = 0; k < HH; ++k) {
        const float hv = s.h_loc[wid][k];              // broadcast LDS
        const float2 wq = *reinterpret_cast<const float2*>(&s.W_q[k][j0]);
        acc.x = fmaf(hv, wq.x, acc.x);
        acc.y = fmaf(hv, wq.y, acc.y);
      }
      float2 qv = make_float2(tanh_f(acc.x), tanh_f(acc.y));
      *reinterpret_cast<float2*>(&g_q[p][n][j0]) = qv;
    }

    // ===== barrier ARRIVE (release q writes) =====
    __threadfence();           // make this thread's q stores visible GPU-wide
    __syncthreads();
    if (tid == 0) atomicAdd(&g_bar, 1);

    // ===== gates = x_t @ W_ih + h @ W_hh + bias  (overlaps other CTAs' q phase) =====
    u64 accg[4];
    #pragma unroll
    for (int m = 0; m < 4; ++m)
      accg[m] = *reinterpret_cast<const u64*>(&s.bias[m * HH + j0]);
    {
      float xreg = (lane < DD) ? __ldg(&x[((size_t)n * T + t) * DD + lane]) : 0.0f;
      #pragma unroll
      for (int d = 0; d < DD; ++d) {
        const u64 xd2 = pack2(__shfl_sync(0xffffffffu, xreg, d));
        #pragma unroll
        for (int m = 0; m < 4; ++m)
          fma2(accg[m], xd2, *reinterpret_cast<const u64*>(&s.W_ih[d][m * HH + j0]));
      }
      #pragma unroll 4
      for (int k = 0; k < HH; ++k) {
        const u64 h2 = pack2(s.h_loc[wid][k]);      // broadcast LDS
        #pragma unroll
        for (int m = 0; m < 4; ++m)
          fma2(accg[m], h2, *reinterpret_cast<const u64*>(&s.W_hh[k][m * HH + j0]));
      }
    }

    // ===== barrier WAIT (acquire others' q) =====
    if (tid == 0) {
      const int target = NCTA * (t + 1);
      while (*((volatile int*)&g_bar) < target) { }
    }
    __syncthreads();

    // ===== phase 2: Aq = A @ q, register-blocked (8 rows/warp, 8-way k-split) =====
    u64 acc[8];
    #pragma unroll
    for (int r = 0; r < 8; ++r) acc[r] = 0ull;

    #pragma unroll 1
    for (int kt = 0; kt < NKT; ++kt) {
      // stage q tile (L2-only loads: q was written by other SMs)
      {
        const float4* src = reinterpret_cast<const float4*>(&g_q[p][kt * KT][0]);
        float4* dst = reinterpret_cast<float4*>(&s.q_tile[0][0]);
        #pragma unroll
        for (int i = 0; i < (KT * HH / 4) / NTH; ++i)
          dst[tid + i * NTH] = __ldcg(src + tid + i * NTH);
      }
      // stage A dup tile (contiguous copy from precomputed pack; A is L2-resident)
      {
        const float4* src = reinterpret_cast<const float4*>(apack_base + (size_t)kt * KT * (2 * ROWS));
        float4* dst = reinterpret_cast<float4*>(&s.A_s[0][0]);
        #pragma unroll
        for (int i = 0; i < (KT * 2 * ROWS / 4) / NTH; ++i)
          dst[tid + i * NTH] = src[tid + i * NTH];
      }
      __syncthreads();

      const int kbase = ks * 16;
      #pragma unroll 4
      for (int kk = 0; kk < 16; ++kk) {
        const int k = kbase + kk;
        // two LDS.128 broadcasts give four {a,a} pairs each for this row group
        const ulonglong2 d01 = *reinterpret_cast<const ulonglong2*>(&s.A_s[k][rg * 16 + 0]);
        const ulonglong2 d23 = *reinterpret_cast<const ulonglong2*>(&s.A_s[k][rg * 16 + 4]);
        const ulonglong2 d45 = *reinterpret_cast<const ulonglong2*>(&s.A_s[k][rg * 16 + 8]);
        const ulonglong2 d67 = *reinterpret_cast<const ulonglong2*>(&s.A_s[k][rg * 16 + 12]);
        const u64 q2 = *reinterpret_cast<const u64*>(&s.q_tile[k][j0]);
        fma2(acc[0], d01.x, q2);
        fma2(acc[1], d01.y, q2);
        fma2(acc[2], d23.x, q2);
        fma2(acc[3], d23.y, q2);
        fma2(acc[4], d45.x, q2);
        fma2(acc[5], d45.y, q2);
        fma2(acc[6], d67.x, q2);
        fma2(acc[7], d67.y, q2);
      }
      __syncthreads();
    }

    // ===== reduce the 8 k-slice partials (reuse q_tile as [8][16][64] buffer) =====
    float* red = &s.q_tile[0][0];
    #pragma unroll
    for (int r = 0; r < 8; ++r)
      *reinterpret_cast<u64*>(&red[((ks << 4) + (rg << 3) + r) * HH + j0]) = acc[r];
    __syncthreads();
    float2 aqv = make_float2(0.0f, 0.0f);
    #pragma unroll
    for (int sl = 0; sl < 8; ++sl) {
      const float2 v = *reinterpret_cast<const float2*>(&red[((sl << 4) + wid) * HH + j0]);
      aqv.x += v.x; aqv.y += v.y;
    }

    // ===== activations + state update (warp wid owns row wid) =====
    {
      const float2 gi = unpack2(accg[0]);
      const float2 gf = unpack2(accg[1]);
      const float2 gg = unpack2(accg[2]);
      const float2 go = unpack2(accg[3]);
      const float2 cold = *reinterpret_cast<const float2*>(&s.c_loc[wid][j0]);

      const float i0 = sigm_f(gi.x), i1 = sigm_f(gi.y);
      const float f0 = sigm_f(gf.x), f1 = sigm_f(gf.y);
      const float gg0 = tanh_f(gg.x), gg1 = tanh_f(gg.y);
      const float o0 = sigm_f(go.x), o1 = sigm_f(go.y);

      const float c0 = f0 * (cold.x + aqv.x) + i0 * gg0;
      const float c1 = f1 * (cold.y + aqv.y) + i1 * gg1;
      const float h0 = o0 * tanh_f(c0);
      const float h1 = o1 * tanh_f(c1);

      *reinterpret_cast<float2*>(&s.c_loc[wid][j0]) = make_float2(c0, c1);
      *reinterpret_cast<float2*>(&s.h_loc[wid][j0]) = make_float2(h0, h1);

      // out[n, t] = h_t @ W_dense + b_dense   (warp reduction)
      float part = h0 * s.W_d[j0] + h1 * s.W_d[j0 + 1];
      #pragma unroll
      for (int off = 16; off > 0; off >>= 1)
        part += __shfl_down_sync(0xffffffffu, part, off);
      if (lane == 0) out[(size_t)n * T + t] = part + bd;
    }
    __syncthreads();   // red buffer reads done; h/c updated before next step's phases
  }

  // ===== self-resetting barrier counter: last CTA to finish zeroes it =====
  if (tid == 0) {
    const int ticket = atomicAdd(&g_bar, 1);
    if (ticket == NCTA * (T + 1) - 1) {
      atomicExch(&g_bar, 0);     // persists to next launch / graph replay
    }
  }
}

extern "C" void kernel_launch(void* const* d_in, const int* in_sizes, int n_in,
                              void* d_out, int out_size) {
  const float* x    = (const float*)d_in[0];
  const float* A    = (const float*)d_in[1];
  const float* W_ih = (const float*)d_in[2];
  const float* W_hh = (const float*)d_in[3];
  const float* bias = (const float*)d_in[4];
  const float* W_q  = (const float*)d_in[5];
  const float* b_q  = (const float*)d_in[6];
  const float* W_d  = (const float*)d_in[7];
  const float* b_d  = (const float*)d_in[8];
  float* out = (float*)d_out;

  const int T = in_sizes[0] / (NN * DD);   // 365

  cudaFuncSetAttribute(rgcn_kernel,
                       cudaFuncAttributeMaxDynamicSharedMemorySize,
                       (int)sizeof(Smem));
  rgcn_kernel<<<NCTA, NTH, sizeof(Smem)>>>(x, A, W_ih, W_hh, bias,
                                           W_q, b_q, W_d, b_d, out, T);
}